// round 4
// baseline (speedup 1.0000x reference)
#include <cuda_runtime.h>
#include <math.h>
#include <stdint.h>

#define BSZ  128
#define NTOK 196
#define CDIM 384
#define KB   16
#define HH   6
#define DR   96   // DIM/R
#define KH   96   // K*H

// scratch for softmaxed mixing coefficients, layout [B][N][K][H]
__device__ __align__(256) float g_mix[BSZ * NTOK * KH];

// ---------------------------------------------------------------------------
// Kernel 1: adapter MLP (Linear -> exact GELU -> Linear) + softmax over K
// (unchanged)
// ---------------------------------------------------------------------------
#define ROWS 32
#define TPB1 256

__global__ __launch_bounds__(TPB1, 2)
void adapter_kernel(const float* __restrict__ x,
                    const float* __restrict__ W1,
                    const float* __restrict__ b1,
                    const float* __restrict__ W2,
                    const float* __restrict__ b2)
{
    __shared__ float xs[ROWS][CDIM];
    __shared__ float hid[ROWS][DR];
    __shared__ float wst[DR * DR];

    const int t    = threadIdx.x;
    const int row0 = blockIdx.x * ROWS;

    {
        const float4* xg = (const float4*)(x + (size_t)row0 * CDIM);
        float4* xd = (float4*)&xs[0][0];
        for (int i = t; i < ROWS * CDIM / 4; i += TPB1) xd[i] = xg[i];
    }

    const int cg = t & 31;
    const int rg = t >> 5;

    float acc[4][3];
    #pragma unroll
    for (int i = 0; i < 4; i++)
        #pragma unroll
        for (int j = 0; j < 3; j++) acc[i][j] = b1[cg * 3 + j];

    for (int kt = 0; kt < CDIM; kt += 32) {
        __syncthreads();
        for (int i = t; i < 32 * DR; i += TPB1) wst[i] = W1[kt * DR + i];
        __syncthreads();
        #pragma unroll
        for (int kk = 0; kk < 32; kk++) {
            float xv[4], wv[3];
            #pragma unroll
            for (int i = 0; i < 4; i++) xv[i] = xs[rg * 4 + i][kt + kk];
            #pragma unroll
            for (int j = 0; j < 3; j++) wv[j] = wst[kk * DR + cg * 3 + j];
            #pragma unroll
            for (int i = 0; i < 4; i++)
                #pragma unroll
                for (int j = 0; j < 3; j++) acc[i][j] += xv[i] * wv[j];
        }
    }

    #pragma unroll
    for (int i = 0; i < 4; i++)
        #pragma unroll
        for (int j = 0; j < 3; j++) {
            float v = acc[i][j];
            hid[rg * 4 + i][cg * 3 + j] = 0.5f * v * (1.0f + erff(v * 0.70710678118654752f));
        }
    __syncthreads();

    for (int i = t; i < DR * DR; i += TPB1) wst[i] = W2[i];
    __syncthreads();

    float acc2[4][3];
    #pragma unroll
    for (int i = 0; i < 4; i++)
        #pragma unroll
        for (int j = 0; j < 3; j++) acc2[i][j] = b2[cg * 3 + j];

    #pragma unroll 4
    for (int k = 0; k < DR; k++) {
        float xv[4], wv[3];
        #pragma unroll
        for (int i = 0; i < 4; i++) xv[i] = hid[rg * 4 + i][k];
        #pragma unroll
        for (int j = 0; j < 3; j++) wv[j] = wst[k * DR + cg * 3 + j];
        #pragma unroll
        for (int i = 0; i < 4; i++)
            #pragma unroll
            for (int j = 0; j < 3; j++) acc2[i][j] += xv[i] * wv[j];
    }

    float* mr = &xs[0][0];
    #pragma unroll
    for (int i = 0; i < 4; i++)
        #pragma unroll
        for (int j = 0; j < 3; j++)
            mr[(rg * 4 + i) * KH + cg * 3 + j] = acc2[i][j];
    __syncthreads();

    if (t < ROWS * HH) {
        const int r = t / HH, h = t % HH;
        const float* p = mr + r * KH + h;
        float mx = -1e30f;
        #pragma unroll
        for (int k = 0; k < KB; k++) mx = fmaxf(mx, p[k * HH]);
        float e[KB], s = 0.0f;
        #pragma unroll
        for (int k = 0; k < KB; k++) { e[k] = expf(p[k * HH] - mx); s += e[k]; }
        const float inv = 1.0f / s;
        float* og = g_mix + (size_t)(row0 + r) * KH + h;
        #pragma unroll
        for (int k = 0; k < KB; k++) og[k * HH] = e[k] * inv;
    }
}

// ---------------------------------------------------------------------------
// Kernel 2 (v4): tensor-core token mixing with 3xTF32 mma.sync.
// Block = (m-half of 112 rows, b). 384 threads = 12 warps = 6 h x 2 c-halves.
// Per 16-n tile: build W^T tile [6h][112m][16n] in smem, then
// D[m,c] += sum_n W^T[m,n] * X[n,c] via mma.m16n8k8 tf32 (hi/lo split).
// ---------------------------------------------------------------------------
#define NTILE   16
#define NKTILES 13         // ceil(196/16)
#define MROWS   112
#define XROW    392        // padded X row (floats) for bank spread
#define WROW    18         // padded W row (floats)
#define TPB2    384

#define XS_OFF  0
#define WS_OFF  (NTILE * XROW)                   // 6272
#define MS_OFF  (WS_OFF + HH * MROWS * WROW)     // 18368
#define SM_FLOATS (MS_OFF + NTILE * KH)          // 19904
#define SM_BYTES  (SM_FLOATS * 4)                // 79616

__device__ __forceinline__ void tf32split(float v, uint32_t& hi, uint32_t& lo) {
    asm("cvt.rna.tf32.f32 %0, %1;" : "=r"(hi) : "f"(v));
    float r = v - __uint_as_float(hi);
    asm("cvt.rna.tf32.f32 %0, %1;" : "=r"(lo) : "f"(r));
}

__device__ __forceinline__ void mma_tf32(float* d, const uint32_t* a, const uint32_t* b) {
    asm volatile(
        "mma.sync.aligned.m16n8k8.row.col.f32.tf32.tf32.f32 "
        "{%0,%1,%2,%3}, {%4,%5,%6,%7}, {%8,%9}, {%0,%1,%2,%3};"
        : "+f"(d[0]), "+f"(d[1]), "+f"(d[2]), "+f"(d[3])
        : "r"(a[0]), "r"(a[1]), "r"(a[2]), "r"(a[3]), "r"(b[0]), "r"(b[1]));
}

__global__ __launch_bounds__(TPB2, 1)
void mix_kernel(const float* __restrict__ x,
                const float* __restrict__ WB,
                float* __restrict__ out)
{
    extern __shared__ __align__(16) float sm[];
    float* xs  = sm + XS_OFF;    // [NTILE][XROW]
    float* ws  = sm + WS_OFF;    // [HH][MROWS][WROW]
    float* msx = sm + MS_OFF;    // [NTILE][KH]

    const int b   = blockIdx.y;
    const int mh  = blockIdx.x;
    const int m0g = mh * MROWS;       // global m base (0 or 112)
    const int t   = threadIdx.x;
    const int lane = t & 31;
    const int w    = t >> 5;
    const int h     = w >> 1;         // head 0..5
    const int chalf = w & 1;          // c half
    const int cofs  = h * 64 + chalf * 32;

    const float* xb = x     + (size_t)b * NTOK * CDIM;
    const float* mb = g_mix + (size_t)b * NTOK * KH;

    float acc[7][4][4];
    #pragma unroll
    for (int mt = 0; mt < 7; mt++)
        #pragma unroll
        for (int ct = 0; ct < 4; ct++)
            #pragma unroll
            for (int j = 0; j < 4; j++) acc[mt][ct][j] = 0.0f;

    for (int it = 0; it < NKTILES; it++) {
        const int n0 = it * NTILE;

        // ---- phase 1: load X tile + mix tile into smem (zero-padded) ----
        #pragma unroll
        for (int i = t; i < NTILE * (CDIM / 4); i += TPB2) {     // 1536 float4
            const int nn = i / (CDIM / 4), q = i % (CDIM / 4);
            float4 v = make_float4(0.f, 0.f, 0.f, 0.f);
            if (n0 + nn < NTOK)
                v = *(const float4*)(xb + (size_t)(n0 + nn) * CDIM + q * 4);
            *(float4*)(xs + nn * XROW + q * 4) = v;
        }
        {   // 16*24 = 384 float4 -> exactly one per thread
            const int nn = t / 24, q = t % 24;
            float4 v = make_float4(0.f, 0.f, 0.f, 0.f);
            if (n0 + nn < NTOK)
                v = *(const float4*)(mb + (size_t)(n0 + nn) * KH + q * 4);
            *(float4*)(msx + nn * KH + q * 4) = v;
        }
        __syncthreads();

        // ---- phase 2: build W^T tile  ws[h][m][nn] ----
        for (int item = t; item < NTILE * (MROWS / 4); item += TPB2) {   // 448
            const int nn = item / (MROWS / 4);
            const int mv = item % (MROWS / 4);
            const int gm = m0g + mv * 4;
            uint64_t wa2[HH][2];
            #pragma unroll
            for (int hh = 0; hh < HH; hh++) { wa2[hh][0] = 0ull; wa2[hh][1] = 0ull; }

            if (gm + 3 < NTOK && n0 + nn < NTOK) {
                const float* wp   = WB + (size_t)(n0 + nn) * NTOK + gm;
                const float* mrow = msx + nn * KH;
                #pragma unroll 4
                for (int k = 0; k < KB; k++) {
                    const float4 w4 = __ldg((const float4*)(wp + (size_t)k * NTOK * NTOK));
                    uint64_t pxy, pzw;
                    asm("mov.b64 %0, {%1,%2};" : "=l"(pxy) : "f"(w4.x), "f"(w4.y));
                    asm("mov.b64 %0, {%1,%2};" : "=l"(pzw) : "f"(w4.z), "f"(w4.w));
                    #pragma unroll
                    for (int hh = 0; hh < HH; hh++) {
                        const float mk = mrow[k * HH + hh];
                        uint64_t mp;
                        asm("mov.b64 %0, {%1,%1};" : "=l"(mp) : "f"(mk));
                        asm("fma.rn.f32x2 %0, %1, %2, %0;" : "+l"(wa2[hh][0]) : "l"(mp), "l"(pxy));
                        asm("fma.rn.f32x2 %0, %1, %2, %0;" : "+l"(wa2[hh][1]) : "l"(mp), "l"(pzw));
                    }
                }
            }
            #pragma unroll
            for (int hh = 0; hh < HH; hh++) {
                float f0, f1, f2, f3;
                asm("mov.b64 {%0,%1}, %2;" : "=f"(f0), "=f"(f1) : "l"(wa2[hh][0]));
                asm("mov.b64 {%0,%1}, %2;" : "=f"(f2), "=f"(f3) : "l"(wa2[hh][1]));
                float* wd = ws + (hh * MROWS + mv * 4) * WROW + nn;
                wd[0] = f0; wd[WROW] = f1; wd[2 * WROW] = f2; wd[3 * WROW] = f3;
            }
        }
        __syncthreads();

        // ---- phase 3: mma over this 16-n tile (two k-steps of 8) ----
        #pragma unroll
        for (int kk = 0; kk < NTILE; kk += 8) {
            // B fragments: B[k][c], col layout: b0 (k=lane%4, c=lane/4), b1 (k+4)
            uint32_t bhi[4][2], blo[4][2];
            const int kr = kk + (lane & 3);
            const int cc = cofs + (lane >> 2);
            #pragma unroll
            for (int ct = 0; ct < 4; ct++) {
                tf32split(xs[kr * XROW + cc + ct * 8],       bhi[ct][0], blo[ct][0]);
                tf32split(xs[(kr + 4) * XROW + cc + ct * 8], bhi[ct][1], blo[ct][1]);
            }
            #pragma unroll
            for (int mt = 0; mt < 7; mt++) {
                // A fragment (row layout): a0(r=l/4,c=l%4) a1(r+8) a2(c+4) a3(r+8,c+4)
                const float* ap = ws + (h * MROWS + mt * 16 + (lane >> 2)) * WROW
                                     + kk + (lane & 3);
                uint32_t ahi[4], alo[4];
                tf32split(ap[0],            ahi[0], alo[0]);
                tf32split(ap[8 * WROW],     ahi[1], alo[1]);
                tf32split(ap[4],            ahi[2], alo[2]);
                tf32split(ap[8 * WROW + 4], ahi[3], alo[3]);
                #pragma unroll
                for (int ct = 0; ct < 4; ct++) {
                    mma_tf32(acc[mt][ct], ahi, bhi[ct]);
                    mma_tf32(acc[mt][ct], alo, bhi[ct]);
                    mma_tf32(acc[mt][ct], ahi, blo[ct]);
                }
            }
        }
        __syncthreads();      // protect smem for next tile
    }

    // ---- epilogue: D rows = m0g + mt*16 + lane/4 (+8), cols = cofs + ct*8 + 2*(lane%4)
    #pragma unroll
    for (int mt = 0; mt < 7; mt++) {
        const int r0 = m0g + mt * 16 + (lane >> 2);
        const int r1 = r0 + 8;
        #pragma unroll
        for (int ct = 0; ct < 4; ct++) {
            const int c = cofs + ct * 8 + 2 * (lane & 3);
            if (r0 < NTOK) {
                float2 v = make_float2(acc[mt][ct][0], acc[mt][ct][1]);
                *(float2*)(out + ((size_t)b * NTOK + r0) * CDIM + c) = v;
            }
            if (r1 < NTOK) {
                float2 v = make_float2(acc[mt][ct][2], acc[mt][ct][3]);
                *(float2*)(out + ((size_t)b * NTOK + r1) * CDIM + c) = v;
            }
        }
    }
}

// ---------------------------------------------------------------------------
extern "C" void kernel_launch(void* const* d_in, const int* in_sizes, int n_in,
                              void* d_out, int out_size)
{
    const float* x  = (const float*)d_in[0];
    const float* W1 = (const float*)d_in[1];
    const float* b1 = (const float*)d_in[2];
    const float* W2 = (const float*)d_in[3];
    const float* b2 = (const float*)d_in[4];
    const float* WB = (const float*)d_in[5];
    float* out = (float*)d_out;

    cudaFuncSetAttribute(mix_kernel, cudaFuncAttributeMaxDynamicSharedMemorySize, SM_BYTES);

    adapter_kernel<<<(BSZ * NTOK) / ROWS, TPB1>>>(x, W1, b1, W2, b2);
    mix_kernel<<<dim3(2, BSZ), TPB2, SM_BYTES>>>(x, WB, out);
}

// round 6
// speedup vs baseline: 1.0129x; 1.0129x over previous
#include <cuda_runtime.h>
#include <math.h>
#include <stdint.h>

#define BSZ  128
#define NTOK 196
#define CDIM 384
#define KB   16
#define HH   6
#define DR   96   // DIM/R
#define KH   96   // K*H

// scratch for softmaxed mixing coefficients, layout [B][N][K][H]
__device__ __align__(256) float g_mix[BSZ * NTOK * KH];

// ---------------------------------------------------------------------------
// Kernel 1: adapter MLP (Linear -> exact GELU -> Linear) + softmax over K
// (unchanged)
// ---------------------------------------------------------------------------
#define ROWS 32
#define TPB1 256

__global__ __launch_bounds__(TPB1, 2)
void adapter_kernel(const float* __restrict__ x,
                    const float* __restrict__ W1,
                    const float* __restrict__ b1,
                    const float* __restrict__ W2,
                    const float* __restrict__ b2)
{
    __shared__ float xs[ROWS][CDIM];
    __shared__ float hid[ROWS][DR];
    __shared__ float wst[DR * DR];

    const int t    = threadIdx.x;
    const int row0 = blockIdx.x * ROWS;

    {
        const float4* xg = (const float4*)(x + (size_t)row0 * CDIM);
        float4* xd = (float4*)&xs[0][0];
        for (int i = t; i < ROWS * CDIM / 4; i += TPB1) xd[i] = xg[i];
    }

    const int cg = t & 31;
    const int rg = t >> 5;

    float acc[4][3];
    #pragma unroll
    for (int i = 0; i < 4; i++)
        #pragma unroll
        for (int j = 0; j < 3; j++) acc[i][j] = b1[cg * 3 + j];

    for (int kt = 0; kt < CDIM; kt += 32) {
        __syncthreads();
        for (int i = t; i < 32 * DR; i += TPB1) wst[i] = W1[kt * DR + i];
        __syncthreads();
        #pragma unroll
        for (int kk = 0; kk < 32; kk++) {
            float xv[4], wv[3];
            #pragma unroll
            for (int i = 0; i < 4; i++) xv[i] = xs[rg * 4 + i][kt + kk];
            #pragma unroll
            for (int j = 0; j < 3; j++) wv[j] = wst[kk * DR + cg * 3 + j];
            #pragma unroll
            for (int i = 0; i < 4; i++)
                #pragma unroll
                for (int j = 0; j < 3; j++) acc[i][j] += xv[i] * wv[j];
        }
    }

    #pragma unroll
    for (int i = 0; i < 4; i++)
        #pragma unroll
        for (int j = 0; j < 3; j++) {
            float v = acc[i][j];
            hid[rg * 4 + i][cg * 3 + j] = 0.5f * v * (1.0f + erff(v * 0.70710678118654752f));
        }
    __syncthreads();

    for (int i = t; i < DR * DR; i += TPB1) wst[i] = W2[i];
    __syncthreads();

    float acc2[4][3];
    #pragma unroll
    for (int i = 0; i < 4; i++)
        #pragma unroll
        for (int j = 0; j < 3; j++) acc2[i][j] = b2[cg * 3 + j];

    #pragma unroll 4
    for (int k = 0; k < DR; k++) {
        float xv[4], wv[3];
        #pragma unroll
        for (int i = 0; i < 4; i++) xv[i] = hid[rg * 4 + i][k];
        #pragma unroll
        for (int j = 0; j < 3; j++) wv[j] = wst[k * DR + cg * 3 + j];
        #pragma unroll
        for (int i = 0; i < 4; i++)
            #pragma unroll
            for (int j = 0; j < 3; j++) acc2[i][j] += xv[i] * wv[j];
    }

    float* mr = &xs[0][0];
    #pragma unroll
    for (int i = 0; i < 4; i++)
        #pragma unroll
        for (int j = 0; j < 3; j++)
            mr[(rg * 4 + i) * KH + cg * 3 + j] = acc2[i][j];
    __syncthreads();

    if (t < ROWS * HH) {
        const int r = t / HH, h = t % HH;
        const float* p = mr + r * KH + h;
        float mx = -1e30f;
        #pragma unroll
        for (int k = 0; k < KB; k++) mx = fmaxf(mx, p[k * HH]);
        float e[KB], s = 0.0f;
        #pragma unroll
        for (int k = 0; k < KB; k++) { e[k] = expf(p[k * HH] - mx); s += e[k]; }
        const float inv = 1.0f / s;
        float* og = g_mix + (size_t)(row0 + r) * KH + h;
        #pragma unroll
        for (int k = 0; k < KB; k++) og[k * HH] = e[k] * inv;
    }
}

// ---------------------------------------------------------------------------
// Kernel 2 (v5): 3xTF32 mma token mixing, re-tiled for occupancy.
// Block = (m-tile of 28 -> padded 32, b). grid (7,128)=896. 384 thr = 12 warps
// = 6 heads x 2 c-halves. 2 blocks/SM for cross-block latency hiding.
// ---------------------------------------------------------------------------
#define NTILE   16
#define NKTILES 13         // ceil(196/16)
#define MR      28         // real m rows per block
#define MPAD    32         // padded for mma
#define XROW    392        // padded X row (floats)
#define WROW    18         // padded W row (floats)
#define TPB2    384

__device__ __forceinline__ void tf32split(float v, uint32_t& hi, uint32_t& lo) {
    asm("cvt.rna.tf32.f32 %0, %1;" : "=r"(hi) : "f"(v));
    float r = v - __uint_as_float(hi);
    asm("cvt.rna.tf32.f32 %0, %1;" : "=r"(lo) : "f"(r));
}

__device__ __forceinline__ void mma_tf32(float* d, const uint32_t* a, const uint32_t* b) {
    asm volatile(
        "mma.sync.aligned.m16n8k8.row.col.f32.tf32.tf32.f32 "
        "{%0,%1,%2,%3}, {%4,%5,%6,%7}, {%8,%9}, {%0,%1,%2,%3};"
        : "+f"(d[0]), "+f"(d[1]), "+f"(d[2]), "+f"(d[3])
        : "r"(a[0]), "r"(a[1]), "r"(a[2]), "r"(a[3]), "r"(b[0]), "r"(b[1]));
}

__global__ __launch_bounds__(TPB2, 2)
void mix_kernel(const float* __restrict__ x,
                const float* __restrict__ WB,
                float* __restrict__ out)
{
    __shared__ float xs[NTILE * XROW];        // 6272 fl
    __shared__ float ws[HH * MPAD * WROW];    // 3456 fl
    __shared__ float msx[NTILE * KH];         // 1536 fl   (total ~44 KB)

    const int b    = blockIdx.y;
    const int m0g  = blockIdx.x * MR;
    const int t    = threadIdx.x;
    const int lane = t & 31;
    const int w    = t >> 5;
    const int h     = w >> 1;           // head 0..5
    const int chalf = w & 1;            // c half (32 cols each)
    const int cofs  = h * 64 + chalf * 32;

    const float* xb = x     + (size_t)b * NTOK * CDIM;
    const float* mb = g_mix + (size_t)b * NTOK * KH;

    // zero pad rows of ws (m 28..31 for every head) - written once, never touched again
    for (int i = t; i < HH * MPAD * WROW; i += TPB2) ws[i] = 0.0f;

    float acc[2][4][4];
    #pragma unroll
    for (int mt = 0; mt < 2; mt++)
        #pragma unroll
        for (int ct = 0; ct < 4; ct++)
            #pragma unroll
            for (int j = 0; j < 4; j++) acc[mt][ct][j] = 0.0f;

    __syncthreads();

    for (int it = 0; it < NKTILES; it++) {
        const int n0 = it * NTILE;

        // ---- phase 1: load X tile (zero-padded) + mix tile ----
        #pragma unroll
        for (int r = 0; r < 4; r++) {                 // 1536 float4 / 384 thr
            const int i = t + r * TPB2;
            const int nn = i / (CDIM / 4), q = i % (CDIM / 4);
            float4 v = make_float4(0.f, 0.f, 0.f, 0.f);
            if (n0 + nn < NTOK)
                v = *(const float4*)(xb + (size_t)(n0 + nn) * CDIM + q * 4);
            *(float4*)(xs + nn * XROW + q * 4) = v;
        }
        {   // 16*24 = 384 float4 -> exactly one per thread
            const int nn = t / 24, q = t % 24;
            float4 v = make_float4(0.f, 0.f, 0.f, 0.f);
            if (n0 + nn < NTOK)
                v = *(const float4*)(mb + (size_t)(n0 + nn) * KH + q * 4);
            *(float4*)(msx + nn * KH + q * 4) = v;
        }
        __syncthreads();

        // ---- phase 2: build W^T tile  ws[h][m][nn] = sum_k mix[n,k,h]*WB[k,n,m]
        if (t < NTILE * (MR / 2)) {                   // 224 items, float2 over m
            const int nn = t / (MR / 2);
            const int mv = t % (MR / 2);
            const int m  = mv * 2;
            float wacc[HH][2];
            #pragma unroll
            for (int hh = 0; hh < HH; hh++) { wacc[hh][0] = 0.f; wacc[hh][1] = 0.f; }

            if (n0 + nn < NTOK) {
                const float2* wp = (const float2*)(WB + (size_t)(n0 + nn) * NTOK + m0g + m);
                const float* mrow = msx + nn * KH;
                #pragma unroll 4
                for (int k = 0; k < KB; k++) {
                    const float2 w2 = __ldg(wp + (size_t)k * (NTOK * NTOK / 2));
                    #pragma unroll
                    for (int hh = 0; hh < HH; hh++) {
                        const float mk = mrow[k * HH + hh];
                        wacc[hh][0] += mk * w2.x;
                        wacc[hh][1] += mk * w2.y;
                    }
                }
            }
            #pragma unroll
            for (int hh = 0; hh < HH; hh++) {
                float* wd = ws + (hh * MPAD + m) * WROW + nn;
                wd[0]    = wacc[hh][0];
                wd[WROW] = wacc[hh][1];
            }
        }
        __syncthreads();

        // ---- phase 3: mma over this 16-n tile (two k-steps of 8) ----
        #pragma unroll
        for (int kk = 0; kk < NTILE; kk += 8) {
            uint32_t bhi[4][2], blo[4][2];
            const int kr = kk + (lane & 3);
            const int cc = cofs + (lane >> 2);
            #pragma unroll
            for (int ct = 0; ct < 4; ct++) {
                tf32split(xs[kr * XROW + cc + ct * 8],       bhi[ct][0], blo[ct][0]);
                tf32split(xs[(kr + 4) * XROW + cc + ct * 8], bhi[ct][1], blo[ct][1]);
            }
            #pragma unroll
            for (int mt = 0; mt < 2; mt++) {
                const float* ap = ws + (h * MPAD + mt * 16 + (lane >> 2)) * WROW
                                     + kk + (lane & 3);
                uint32_t ahi[4], alo[4];
                tf32split(ap[0],            ahi[0], alo[0]);
                tf32split(ap[8 * WROW],     ahi[1], alo[1]);
                tf32split(ap[4],            ahi[2], alo[2]);
                tf32split(ap[8 * WROW + 4], ahi[3], alo[3]);
                #pragma unroll
                for (int ct = 0; ct < 4; ct++) {
                    mma_tf32(acc[mt][ct], ahi, bhi[ct]);
                    mma_tf32(acc[mt][ct], alo, bhi[ct]);
                    mma_tf32(acc[mt][ct], ahi, blo[ct]);
                }
            }
        }
        __syncthreads();      // protect smem for next tile
    }

    // ---- epilogue ----
    #pragma unroll
    for (int mt = 0; mt < 2; mt++) {
        const int lr0 = mt * 16 + (lane >> 2);       // 0..23, always valid
        const int lr1 = lr0 + 8;                     // up to 31, guard < MR
        #pragma unroll
        for (int ct = 0; ct < 4; ct++) {
            const int c = cofs + ct * 8 + 2 * (lane & 3);
            *(float2*)(out + ((size_t)b * NTOK + m0g + lr0) * CDIM + c) =
                make_float2(acc[mt][ct][0], acc[mt][ct][1]);
            if (lr1 < MR)
                *(float2*)(out + ((size_t)b * NTOK + m0g + lr1) * CDIM + c) =
                    make_float2(acc[mt][ct][2], acc[mt][ct][3]);
        }
    }
}

// ---------------------------------------------------------------------------
extern "C" void kernel_launch(void* const* d_in, const int* in_sizes, int n_in,
                              void* d_out, int out_size)
{
    const float* x  = (const float*)d_in[0];
    const float* W1 = (const float*)d_in[1];
    const float* b1 = (const float*)d_in[2];
    const float* W2 = (const float*)d_in[3];
    const float* b2 = (const float*)d_in[4];
    const float* WB = (const float*)d_in[5];
    float* out = (float*)d_out;

    adapter_kernel<<<(BSZ * NTOK) / ROWS, TPB1>>>(x, W1, b1, W2, b2);
    mix_kernel<<<dim3(NTOK / MR, BSZ), TPB2>>>(x, WB, out);
}

// round 8
// speedup vs baseline: 1.2547x; 1.2387x over previous
#include <cuda_runtime.h>
#include <math.h>
#include <stdint.h>

#define BSZ  128
#define NTOK 196
#define CDIM 384
#define KB   16
#define HH   6
#define DR   96   // DIM/R
#define KH   96   // K*H

__device__ __align__(256) float g_mix[BSZ * NTOK * KH];

// ---------------- packed f32x2 helpers ----------------
__device__ __forceinline__ uint64_t pk2(float a, float b) {
    uint64_t r; asm("mov.b64 %0,{%1,%2};" : "=l"(r) : "f"(a), "f"(b)); return r;
}
__device__ __forceinline__ void up2(uint64_t v, float& a, float& b) {
    asm("mov.b64 {%0,%1},%2;" : "=f"(a), "=f"(b) : "l"(v));
}
__device__ __forceinline__ void fma2(uint64_t& d, uint64_t a, uint64_t b) {
    asm("fma.rn.f32x2 %0,%1,%2,%0;" : "+l"(d) : "l"(a), "l"(b));
}
__device__ __forceinline__ uint32_t smem_u32(const void* p) {
    uint32_t a;
    asm("{ .reg .u64 t; cvta.to.shared.u64 t, %1; cvt.u32.u64 %0, t; }" : "=r"(a) : "l"(p));
    return a;
}
#define MBAR_WAIT(addr, par) do {                                             \
    uint32_t _done;                                                           \
    asm volatile("{\n\t.reg .pred p;\n\t"                                     \
        "mbarrier.try_wait.parity.acquire.cta.shared::cta.b64 p, [%1], %2;\n\t" \
        "selp.b32 %0, 1, 0, p;\n\t}" : "=r"(_done) : "r"(addr), "r"(par) : "memory"); \
    if (!_done) {                                                             \
        asm volatile("{\n\t.reg .pred P1;\n\t"                                \
            "W_%=:\n\t"                                                       \
            "mbarrier.try_wait.parity.acquire.cta.shared::cta.b64 P1, [%0], %1, 0x989680;\n\t" \
            "@P1 bra.uni D_%=;\n\t"                                           \
            "bra.uni W_%=;\n\t"                                               \
            "D_%=:\n\t}" :: "r"(addr), "r"(par) : "memory");                  \
    }                                                                         \
} while (0)

// ---------------------------------------------------------------------------
// Kernel 1: adapter MLP + softmax. v2: conflict-free wst cols + f32x2 math.
// ---------------------------------------------------------------------------
#define ROWS 32
#define TPB1 256

__global__ __launch_bounds__(TPB1, 2)
void adapter_kernel(const float* __restrict__ x,
                    const float* __restrict__ W1,
                    const float* __restrict__ b1,
                    const float* __restrict__ W2,
                    const float* __restrict__ b2)
{
    __shared__ float xs[ROWS][CDIM];
    __shared__ float hid[ROWS][DR];
    __shared__ float wst[DR * DR];

    const int t    = threadIdx.x;
    const int row0 = blockIdx.x * ROWS;

    {
        const float4* xg = (const float4*)(x + (size_t)row0 * CDIM);
        float4* xd = (float4*)&xs[0][0];
        for (int i = t; i < ROWS * CDIM / 4; i += TPB1) xd[i] = xg[i];
    }

    const int cg = t & 31;   // owns cols cg + 32*j (stride-1 across lanes)
    const int rg = t >> 5;   // owns rows rg*4 + i

    // ---- GEMM1: hid = x @ W1 + b1 (packed rows (0,1),(2,3)) ----
    uint64_t a01[3], a23[3];
    #pragma unroll
    for (int j = 0; j < 3; j++) {
        const float bv = b1[cg + 32 * j];
        a01[j] = pk2(bv, bv);
        a23[j] = pk2(bv, bv);
    }

    for (int kt = 0; kt < CDIM; kt += 32) {
        __syncthreads();
        for (int i = t; i < 32 * DR; i += TPB1) wst[i] = W1[kt * DR + i];
        __syncthreads();
        #pragma unroll
        for (int kk = 0; kk < 32; kk++) {
            const float x0 = xs[rg * 4 + 0][kt + kk];
            const float x1 = xs[rg * 4 + 1][kt + kk];
            const float x2 = xs[rg * 4 + 2][kt + kk];
            const float x3 = xs[rg * 4 + 3][kt + kk];
            const uint64_t x01 = pk2(x0, x1), x23 = pk2(x2, x3);
            #pragma unroll
            for (int j = 0; j < 3; j++) {
                const float wv = wst[kk * DR + cg + 32 * j];
                const uint64_t wq = pk2(wv, wv);
                fma2(a01[j], x01, wq);
                fma2(a23[j], x23, wq);
            }
        }
    }

    // ---- exact GELU ----
    #pragma unroll
    for (int j = 0; j < 3; j++) {
        float g0, g1, g2, g3;
        up2(a01[j], g0, g1); up2(a23[j], g2, g3);
        const int c = cg + 32 * j;
        hid[rg * 4 + 0][c] = 0.5f * g0 * (1.0f + erff(g0 * 0.70710678118654752f));
        hid[rg * 4 + 1][c] = 0.5f * g1 * (1.0f + erff(g1 * 0.70710678118654752f));
        hid[rg * 4 + 2][c] = 0.5f * g2 * (1.0f + erff(g2 * 0.70710678118654752f));
        hid[rg * 4 + 3][c] = 0.5f * g3 * (1.0f + erff(g3 * 0.70710678118654752f));
    }
    __syncthreads();

    // ---- GEMM2 ----
    for (int i = t; i < DR * DR; i += TPB1) wst[i] = W2[i];
    __syncthreads();

    uint64_t c01[3], c23[3];
    #pragma unroll
    for (int j = 0; j < 3; j++) {
        const float bv = b2[cg + 32 * j];
        c01[j] = pk2(bv, bv);
        c23[j] = pk2(bv, bv);
    }

    #pragma unroll 4
    for (int k = 0; k < DR; k++) {
        const float h0 = hid[rg * 4 + 0][k];
        const float h1 = hid[rg * 4 + 1][k];
        const float h2 = hid[rg * 4 + 2][k];
        const float h3 = hid[rg * 4 + 3][k];
        const uint64_t h01 = pk2(h0, h1), h23 = pk2(h2, h3);
        #pragma unroll
        for (int j = 0; j < 3; j++) {
            const float wv = wst[k * DR + cg + 32 * j];
            const uint64_t wq = pk2(wv, wv);
            fma2(c01[j], h01, wq);
            fma2(c23[j], h23, wq);
        }
    }

    float* mr = &xs[0][0];
    #pragma unroll
    for (int j = 0; j < 3; j++) {
        float g0, g1, g2, g3;
        up2(c01[j], g0, g1); up2(c23[j], g2, g3);
        const int c = cg + 32 * j;
        mr[(rg * 4 + 0) * KH + c] = g0;
        mr[(rg * 4 + 1) * KH + c] = g1;
        mr[(rg * 4 + 2) * KH + c] = g2;
        mr[(rg * 4 + 3) * KH + c] = g3;
    }
    __syncthreads();

    // ---- softmax over k (stride H) per (row, h) ----
    if (t < ROWS * HH) {
        const int r = t / HH, h = t % HH;
        const float* p = mr + r * KH + h;
        float mx = -1e30f;
        #pragma unroll
        for (int k = 0; k < KB; k++) mx = fmaxf(mx, p[k * HH]);
        float e[KB], s = 0.0f;
        #pragma unroll
        for (int k = 0; k < KB; k++) { e[k] = expf(p[k * HH] - mx); s += e[k]; }
        const float inv = 1.0f / s;
        float* og = g_mix + (size_t)(row0 + r) * KH + h;
        #pragma unroll
        for (int k = 0; k < KB; k++) og[k * HH] = e[k] * inv;
    }
}

// ---------------------------------------------------------------------------
// Kernel 2 (v6): SIMT f32x2 mixing with fully pipelined build.
// TMA double-buffered xs/ms, register-staged WB prefetch, double-buffered ws.
// One __syncthreads per n-tile. 224 thr: warps 0-5 compute, all build.
// ---------------------------------------------------------------------------
#define NT      16
#define NTILES  13          // ceil(196/16)
#define MT      28
#define TPB2    224

#define XS_F    (NT * CDIM)       // 6144
#define MS_F    (NT * KH)         // 1536
#define WS_F    (NT * HH * 32)    // 3072
#define SMEM_B  (2 * (XS_F + MS_F + WS_F) * 4)   // 86016 B

__global__ __launch_bounds__(TPB2, 2)
void mix_kernel(const float* __restrict__ x,
                const float* __restrict__ WB,
                float* __restrict__ out)
{
    extern __shared__ __align__(128) float sm[];
    float* xs = sm;                        // [2][NT][CDIM]
    float* ms = sm + 2 * XS_F;             // [2][NT][KH]
    float* ws = sm + 2 * (XS_F + MS_F);    // [2][NT][HH][32]
    __shared__ __align__(16) uint64_t mbar[2];

    const int b    = blockIdx.y;
    const int m0   = blockIdx.x * MT;
    const int t    = threadIdx.x;
    const int lane = t & 31;
    const int h    = t >> 5;          // warps 0-5 compute heads; warp 6 build-only
    const int mt   = lane >> 3;
    const int ct   = lane & 7;

    // build item: 224 = 16 n x 14 m-pairs
    const int nn_i = t / 14;          // 0..15
    const int lm   = 2 * (t % 14);    // local m (even)
    const int s0   = (lm / 7) * 8 + lm % 7;
    const int s1   = ((lm + 1) / 7) * 8 + (lm + 1) % 7;

    const float* xb = x     + (size_t)b * NTOK * CDIM;
    const float* mb = g_mix + (size_t)b * NTOK * KH;
    const size_t NN2 = (size_t)NTOK * NTOK / 2;

    if (t == 0) {
        asm volatile("mbarrier.init.shared.b64 [%0], 1;" :: "r"(smem_u32(&mbar[0])) : "memory");
        asm volatile("mbarrier.init.shared.b64 [%0], 1;" :: "r"(smem_u32(&mbar[1])) : "memory");
    }
    __syncthreads();

    // ---- TMA tile 0 ----
    if (t == 0) {
        uint32_t mba = smem_u32(&mbar[0]);
        asm volatile("mbarrier.arrive.expect_tx.shared.b64 _, [%0], %1;"
                     :: "r"(mba), "r"(NT * (CDIM + KH) * 4) : "memory");
        asm volatile("cp.async.bulk.shared::cta.global.mbarrier::complete_tx::bytes [%0], [%1], %2, [%3];"
                     :: "r"(smem_u32(xs)), "l"(xb), "r"(NT * CDIM * 4), "r"(mba) : "memory");
        asm volatile("cp.async.bulk.shared::cta.global.mbarrier::complete_tx::bytes [%0], [%1], %2, [%3];"
                     :: "r"(smem_u32(ms)), "l"(mb), "r"(NT * KH * 4), "r"(mba) : "memory");
    }

    uint64_t acc[7][4];
    #pragma unroll
    for (int i = 0; i < 7; i++)
        #pragma unroll
        for (int j = 0; j < 4; j++) acc[i][j] = 0ull;

    int ph0 = 0, ph1 = 0;

    // ---- wait tile 0 + prologue build of ws[0] ----
    MBAR_WAIT(smem_u32(&mbar[0]), 0);
    ph0 = 1;
    {
        const float2* wp = (const float2*)(WB + (size_t)nn_i * NTOK + m0 + lm);
        const float* msn = ms + nn_i * KH;
        uint64_t wacc[HH];
        #pragma unroll
        for (int hh = 0; hh < HH; hh++) wacc[hh] = 0ull;
        #pragma unroll 4
        for (int k = 0; k < KB; k++) {
            const float2 w2 = __ldg(wp + k * NN2);
            const uint64_t wq = pk2(w2.x, w2.y);
            const float2 m01 = *(const float2*)(msn + k * HH);
            const float2 m23 = *(const float2*)(msn + k * HH + 2);
            const float2 m45 = *(const float2*)(msn + k * HH + 4);
            fma2(wacc[0], pk2(m01.x, m01.x), wq);
            fma2(wacc[1], pk2(m01.y, m01.y), wq);
            fma2(wacc[2], pk2(m23.x, m23.x), wq);
            fma2(wacc[3], pk2(m23.y, m23.y), wq);
            fma2(wacc[4], pk2(m45.x, m45.x), wq);
            fma2(wacc[5], pk2(m45.y, m45.y), wq);
        }
        #pragma unroll
        for (int hh = 0; hh < HH; hh++) {
            float f0, f1; up2(wacc[hh], f0, f1);
            float* wd = ws + (nn_i * HH + hh) * 32;
            wd[s0] = f0; wd[s1] = f1;
        }
    }
    __syncthreads();

    for (int it = 0; it < NTILES; it++) {
        const int buf = it & 1, nb = buf ^ 1, jt = it + 1;
        const bool hn = jt < NTILES;

        // 1. TMA prefetch tile jt
        if (t == 0 && hn) {
            const int vn = (jt * NT + NT <= NTOK) ? NT : (NTOK - jt * NT);
            uint32_t mba = smem_u32(&mbar[nb]);
            asm volatile("mbarrier.arrive.expect_tx.shared.b64 _, [%0], %1;"
                         :: "r"(mba), "r"(vn * (CDIM + KH) * 4) : "memory");
            asm volatile("cp.async.bulk.shared::cta.global.mbarrier::complete_tx::bytes [%0], [%1], %2, [%3];"
                         :: "r"(smem_u32(xs + nb * XS_F)), "l"(xb + (size_t)jt * NT * CDIM),
                            "r"(vn * CDIM * 4), "r"(mba) : "memory");
            asm volatile("cp.async.bulk.shared::cta.global.mbarrier::complete_tx::bytes [%0], [%1], %2, [%3];"
                         :: "r"(smem_u32(ms + nb * MS_F)), "l"(mb + (size_t)jt * NT * KH),
                            "r"(vn * KH * 4), "r"(mba) : "memory");
        }

        // 2. WB prefetch into regs for tile jt (in flight during compute)
        float2 wb2[KB];
        const int bn = jt * NT + nn_i;
        const bool bv = hn && (bn < NTOK);
        if (bv) {
            const float2* wp = (const float2*)(WB + (size_t)bn * NTOK + m0 + lm);
            #pragma unroll
            for (int k = 0; k < KB; k++) wb2[k] = __ldg(wp + k * NN2);
        }

        // 3. compute current tile
        if (t < 192) {
            const float* xsb = xs + buf * XS_F;
            const float* wsb = ws + buf * WS_F;
            #pragma unroll 2
            for (int n = 0; n < NT; n++) {
                const float* xr = xsb + n * CDIM + h * 64 + ct * 8;
                const ulonglong2 xa = *(const ulonglong2*)xr;
                const ulonglong2 xc = *(const ulonglong2*)(xr + 4);
                const uint64_t xq[4] = {xa.x, xa.y, xc.x, xc.y};

                const float* wbase = wsb + (n * HH + h) * 32 + mt * 8;
                const float4 w03 = *(const float4*)wbase;
                const float2 w45 = *(const float2*)(wbase + 4);
                const float  w6  = wbase[6];
                const float wv[7] = {w03.x, w03.y, w03.z, w03.w, w45.x, w45.y, w6};

                uint64_t wp7[7];
                #pragma unroll
                for (int i = 0; i < 7; i++) wp7[i] = pk2(wv[i], wv[i]);

                #pragma unroll
                for (int i = 0; i < 7; i++)
                    #pragma unroll
                    for (int j = 0; j < 4; j++)
                        fma2(acc[i][j], wp7[i], xq[j]);
            }
        }

        // 4+5. wait tile jt, build ws[nb]
        if (hn) {
            {
                uint32_t mba = smem_u32(&mbar[nb]);
                const int par = nb ? ph1 : ph0;
                MBAR_WAIT(mba, par);
                if (nb) ph1 ^= 1; else ph0 ^= 1;
            }
            uint64_t wacc[HH];
            #pragma unroll
            for (int hh = 0; hh < HH; hh++) wacc[hh] = 0ull;
            if (bv) {
                const float* msn = ms + nb * MS_F + nn_i * KH;
                #pragma unroll 4
                for (int k = 0; k < KB; k++) {
                    const uint64_t wq = pk2(wb2[k].x, wb2[k].y);
                    const float2 m01 = *(const float2*)(msn + k * HH);
                    const float2 m23 = *(const float2*)(msn + k * HH + 2);
                    const float2 m45 = *(const float2*)(msn + k * HH + 4);
                    fma2(wacc[0], pk2(m01.x, m01.x), wq);
                    fma2(wacc[1], pk2(m01.y, m01.y), wq);
                    fma2(wacc[2], pk2(m23.x, m23.x), wq);
                    fma2(wacc[3], pk2(m23.y, m23.y), wq);
                    fma2(wacc[4], pk2(m45.x, m45.x), wq);
                    fma2(wacc[5], pk2(m45.y, m45.y), wq);
                }
            }
            float* wsn = ws + nb * WS_F;
            #pragma unroll
            for (int hh = 0; hh < HH; hh++) {
                float f0, f1; up2(wacc[hh], f0, f1);
                float* wd = wsn + (nn_i * HH + hh) * 32;
                wd[s0] = f0; wd[s1] = f1;
            }
        }
        __syncthreads();
    }

    // ---- epilogue: out[b][m0 + mt*7 + i][h*64 + ct*8 + j] ----
    if (t < 192) {
        #pragma unroll
        for (int i = 0; i < 7; i++) {
            const int m = m0 + mt * 7 + i;
            float* o = out + ((size_t)b * NTOK + m) * CDIM + h * 64 + ct * 8;
            float4 o1, o2;
            up2(acc[i][0], o1.x, o1.y);
            up2(acc[i][1], o1.z, o1.w);
            up2(acc[i][2], o2.x, o2.y);
            up2(acc[i][3], o2.z, o2.w);
            *(float4*)(o)     = o1;
            *(float4*)(o + 4) = o2;
        }
    }
}

// ---------------------------------------------------------------------------
extern "C" void kernel_launch(void* const* d_in, const int* in_sizes, int n_in,
                              void* d_out, int out_size)
{
    const float* x  = (const float*)d_in[0];
    const float* W1 = (const float*)d_in[1];
    const float* b1 = (const float*)d_in[2];
    const float* W2 = (const float*)d_in[3];
    const float* b2 = (const float*)d_in[4];
    const float* WB = (const float*)d_in[5];
    float* out = (float*)d_out;

    cudaFuncSetAttribute(mix_kernel, cudaFuncAttributeMaxDynamicSharedMemorySize, SMEM_B);

    adapter_kernel<<<(BSZ * NTOK) / ROWS, TPB1>>>(x, W1, b1, W2, b2);
    mix_kernel<<<dim3(NTOK / MT, BSZ), TPB2, SMEM_B>>>(x, WB, out);
}

// round 11
// speedup vs baseline: 1.3242x; 1.0554x over previous
#include <cuda_runtime.h>
#include <math.h>
#include <stdint.h>

#define BSZ  128
#define NTOK 196
#define CDIM 384
#define KB   16
#define HH   6
#define DR   96   // DIM/R
#define KH   96   // K*H

__device__ __align__(256) float g_mix[BSZ * NTOK * KH];

// ---------------- packed f32x2 helpers ----------------
__device__ __forceinline__ uint64_t pk2(float a, float b) {
    uint64_t r; asm("mov.b64 %0,{%1,%2};" : "=l"(r) : "f"(a), "f"(b)); return r;
}
__device__ __forceinline__ void up2(uint64_t v, float& a, float& b) {
    asm("mov.b64 {%0,%1},%2;" : "=f"(a), "=f"(b) : "l"(v));
}
__device__ __forceinline__ void fma2(uint64_t& d, uint64_t a, uint64_t b) {
    asm("fma.rn.f32x2 %0,%1,%2,%0;" : "+l"(d) : "l"(a), "l"(b));
}
__device__ __forceinline__ uint32_t smem_u32(const void* p) {
    uint32_t a;
    asm("{ .reg .u64 t; cvta.to.shared.u64 t, %1; cvt.u32.u64 %0, t; }" : "=r"(a) : "l"(p));
    return a;
}
#define MBAR_WAIT(addr, par) do {                                             \
    uint32_t _done;                                                           \
    asm volatile("{\n\t.reg .pred p;\n\t"                                     \
        "mbarrier.try_wait.parity.acquire.cta.shared::cta.b64 p, [%1], %2;\n\t" \
        "selp.b32 %0, 1, 0, p;\n\t}" : "=r"(_done) : "r"(addr), "r"(par) : "memory"); \
    if (!_done) {                                                             \
        asm volatile("{\n\t.reg .pred P1;\n\t"                                \
            "W_%=:\n\t"                                                       \
            "mbarrier.try_wait.parity.acquire.cta.shared::cta.b64 P1, [%0], %1, 0x989680;\n\t" \
            "@P1 bra.uni D_%=;\n\t"                                           \
            "bra.uni W_%=;\n\t"                                               \
            "D_%=:\n\t}" :: "r"(addr), "r"(par) : "memory");                  \
    }                                                                         \
} while (0)

// ---------------------------------------------------------------------------
// Kernel 1: adapter MLP + softmax (unchanged — passed at rel_err 2.17e-7)
// ---------------------------------------------------------------------------
#define ROWS 32
#define TPB1 256

__global__ __launch_bounds__(TPB1, 2)
void adapter_kernel(const float* __restrict__ x,
                    const float* __restrict__ W1,
                    const float* __restrict__ b1,
                    const float* __restrict__ W2,
                    const float* __restrict__ b2)
{
    __shared__ float xs[ROWS][CDIM];
    __shared__ float hid[ROWS][DR];
    __shared__ float wst[DR * DR];

    const int t    = threadIdx.x;
    const int row0 = blockIdx.x * ROWS;

    {
        const float4* xg = (const float4*)(x + (size_t)row0 * CDIM);
        float4* xd = (float4*)&xs[0][0];
        for (int i = t; i < ROWS * CDIM / 4; i += TPB1) xd[i] = xg[i];
    }

    const int cg = t & 31;
    const int rg = t >> 5;

    uint64_t a01[3], a23[3];
    #pragma unroll
    for (int j = 0; j < 3; j++) {
        const float bv = b1[cg + 32 * j];
        a01[j] = pk2(bv, bv);
        a23[j] = pk2(bv, bv);
    }

    for (int kt = 0; kt < CDIM; kt += 32) {
        __syncthreads();
        for (int i = t; i < 32 * DR; i += TPB1) wst[i] = W1[kt * DR + i];
        __syncthreads();
        #pragma unroll
        for (int kk = 0; kk < 32; kk++) {
            const float x0 = xs[rg * 4 + 0][kt + kk];
            const float x1 = xs[rg * 4 + 1][kt + kk];
            const float x2 = xs[rg * 4 + 2][kt + kk];
            const float x3 = xs[rg * 4 + 3][kt + kk];
            const uint64_t x01 = pk2(x0, x1), x23 = pk2(x2, x3);
            #pragma unroll
            for (int j = 0; j < 3; j++) {
                const float wv = wst[kk * DR + cg + 32 * j];
                const uint64_t wq = pk2(wv, wv);
                fma2(a01[j], x01, wq);
                fma2(a23[j], x23, wq);
            }
        }
    }

    #pragma unroll
    for (int j = 0; j < 3; j++) {
        float g0, g1, g2, g3;
        up2(a01[j], g0, g1); up2(a23[j], g2, g3);
        const int c = cg + 32 * j;
        hid[rg * 4 + 0][c] = 0.5f * g0 * (1.0f + erff(g0 * 0.70710678118654752f));
        hid[rg * 4 + 1][c] = 0.5f * g1 * (1.0f + erff(g1 * 0.70710678118654752f));
        hid[rg * 4 + 2][c] = 0.5f * g2 * (1.0f + erff(g2 * 0.70710678118654752f));
        hid[rg * 4 + 3][c] = 0.5f * g3 * (1.0f + erff(g3 * 0.70710678118654752f));
    }
    __syncthreads();

    for (int i = t; i < DR * DR; i += TPB1) wst[i] = W2[i];
    __syncthreads();

    uint64_t c01[3], c23[3];
    #pragma unroll
    for (int j = 0; j < 3; j++) {
        const float bv = b2[cg + 32 * j];
        c01[j] = pk2(bv, bv);
        c23[j] = pk2(bv, bv);
    }

    #pragma unroll 4
    for (int k = 0; k < DR; k++) {
        const float h0 = hid[rg * 4 + 0][k];
        const float h1 = hid[rg * 4 + 1][k];
        const float h2 = hid[rg * 4 + 2][k];
        const float h3 = hid[rg * 4 + 3][k];
        const uint64_t h01 = pk2(h0, h1), h23 = pk2(h2, h3);
        #pragma unroll
        for (int j = 0; j < 3; j++) {
            const float wv = wst[k * DR + cg + 32 * j];
            const uint64_t wq = pk2(wv, wv);
            fma2(c01[j], h01, wq);
            fma2(c23[j], h23, wq);
        }
    }

    float* mr = &xs[0][0];
    #pragma unroll
    for (int j = 0; j < 3; j++) {
        float g0, g1, g2, g3;
        up2(c01[j], g0, g1); up2(c23[j], g2, g3);
        const int c = cg + 32 * j;
        mr[(rg * 4 + 0) * KH + c] = g0;
        mr[(rg * 4 + 1) * KH + c] = g1;
        mr[(rg * 4 + 2) * KH + c] = g2;
        mr[(rg * 4 + 3) * KH + c] = g3;
    }
    __syncthreads();

    if (t < ROWS * HH) {
        const int r = t / HH, h = t % HH;
        const float* p = mr + r * KH + h;
        float mx = -1e30f;
        #pragma unroll
        for (int k = 0; k < KB; k++) mx = fmaxf(mx, p[k * HH]);
        float e[KB], s = 0.0f;
        #pragma unroll
        for (int k = 0; k < KB; k++) { e[k] = expf(p[k * HH] - mx); s += e[k]; }
        const float inv = 1.0f / s;
        float* og = g_mix + (size_t)(row0 + r) * KH + h;
        #pragma unroll
        for (int k = 0; k < KB; k++) og[k * HH] = e[k] * inv;
    }
}

// ---------------------------------------------------------------------------
// Kernel 2 (v7): r3 base + double-buffered ws + single sync per tile.
// Order per tile: TMA-issue(it+1) -> compute(it) -> wait(it+1) -> build(it+1).
// No register WB prefetch (keeps regs ~r3 level). 192 thr, 3 blocks/SM.
// ---------------------------------------------------------------------------
#define NT      14
#define NTILES  14          // 196/14 exact
#define MT      28
#define TPB2    192

#define XS_F    (NT * CDIM)       // 5376
#define MS_F    (NT * KH)         // 1344
#define WS_F    (NT * HH * 32)    // 2688
#define SMEM_B  (2 * (XS_F + MS_F + WS_F) * 4)   // 75264 B

__global__ __launch_bounds__(TPB2, 3)
void mix_kernel(const float* __restrict__ x,
                const float* __restrict__ WB,
                float* __restrict__ out)
{
    extern __shared__ __align__(128) float sm[];
    float* xs = sm;                        // [2][NT][CDIM]
    float* ms = sm + 2 * XS_F;             // [2][NT][KH]
    float* ws = sm + 2 * (XS_F + MS_F);    // [2][NT][HH][32]
    __shared__ __align__(16) uint64_t mbar[2];

    const int b    = blockIdx.y;
    const int m0   = blockIdx.x * MT;
    const int t    = threadIdx.x;
    const int lane = t & 31;
    const int h    = t >> 5;          // warp == head, 0..5
    const int mt   = lane >> 3;       // m-group
    const int ct   = lane & 7;        // c-group (8 cols)

    const float* xb = x     + (size_t)b * NTOK * CDIM;
    const float* mb = g_mix + (size_t)b * NTOK * KH;
    const size_t NN2 = (size_t)NTOK * NTOK / 2;

    if (t == 0) {
        asm volatile("mbarrier.init.shared.b64 [%0], 1;" :: "r"(smem_u32(&mbar[0])) : "memory");
        asm volatile("mbarrier.init.shared.b64 [%0], 1;" :: "r"(smem_u32(&mbar[1])) : "memory");
    }
    __syncthreads();

    // ---- TMA tile 0 ----
    if (t == 0) {
        uint32_t mba = smem_u32(&mbar[0]);
        asm volatile("mbarrier.arrive.expect_tx.shared.b64 _, [%0], %1;"
                     :: "r"(mba), "r"(NT * (CDIM + KH) * 4) : "memory");
        asm volatile("cp.async.bulk.shared::cta.global.mbarrier::complete_tx::bytes [%0], [%1], %2, [%3];"
                     :: "r"(smem_u32(xs)), "l"(xb), "r"(NT * CDIM * 4), "r"(mba) : "memory");
        asm volatile("cp.async.bulk.shared::cta.global.mbarrier::complete_tx::bytes [%0], [%1], %2, [%3];"
                     :: "r"(smem_u32(ms)), "l"(mb), "r"(NT * KH * 4), "r"(mba) : "memory");
    }

    uint64_t acc[7][4];
    #pragma unroll
    for (int i = 0; i < 7; i++)
        #pragma unroll
        for (int j = 0; j < 4; j++) acc[i][j] = 0ull;

    int ph[2] = {0, 0};

    // ---- prologue: wait tile 0, build ws[0] ----
    MBAR_WAIT(smem_u32(&mbar[0]), 0);
    ph[0] = 1;
    for (int p = t; p < NT * (MT / 2); p += TPB2) {       // 196 items
        const int nn = p / (MT / 2);
        const int lm = 2 * (p % (MT / 2));
        const int s0 = (lm / 7) * 8 + lm % 7;
        const int s1 = ((lm + 1) / 7) * 8 + (lm + 1) % 7;
        const float2* wp = (const float2*)(WB + (size_t)nn * NTOK + m0 + lm);
        const float* msn = ms + nn * KH;
        uint64_t wacc[HH];
        #pragma unroll
        for (int hh = 0; hh < HH; hh++) wacc[hh] = 0ull;
        #pragma unroll 4
        for (int k = 0; k < KB; k++) {
            const float2 w2 = __ldg(wp + k * NN2);
            const uint64_t wq = pk2(w2.x, w2.y);
            const float2 m01 = *(const float2*)(msn + k * HH);
            const float2 m23 = *(const float2*)(msn + k * HH + 2);
            const float2 m45 = *(const float2*)(msn + k * HH + 4);
            fma2(wacc[0], pk2(m01.x, m01.x), wq);
            fma2(wacc[1], pk2(m01.y, m01.y), wq);
            fma2(wacc[2], pk2(m23.x, m23.x), wq);
            fma2(wacc[3], pk2(m23.y, m23.y), wq);
            fma2(wacc[4], pk2(m45.x, m45.x), wq);
            fma2(wacc[5], pk2(m45.y, m45.y), wq);
        }
        #pragma unroll
        for (int hh = 0; hh < HH; hh++) {
            float f0, f1; up2(wacc[hh], f0, f1);
            float* wd = ws + (nn * HH + hh) * 32;
            wd[s0] = f0; wd[s1] = f1;
        }
    }
    __syncthreads();

    for (int it = 0; it < NTILES; it++) {
        const int buf = it & 1, nb = buf ^ 1, jt = it + 1;
        const bool hn = jt < NTILES;

        // 1. TMA prefetch tile jt into nb (nb's xs/ms last read before prev sync)
        if (t == 0 && hn) {
            uint32_t mba = smem_u32(&mbar[nb]);
            asm volatile("mbarrier.arrive.expect_tx.shared.b64 _, [%0], %1;"
                         :: "r"(mba), "r"(NT * (CDIM + KH) * 4) : "memory");
            asm volatile("cp.async.bulk.shared::cta.global.mbarrier::complete_tx::bytes [%0], [%1], %2, [%3];"
                         :: "r"(smem_u32(xs + nb * XS_F)), "l"(xb + (size_t)jt * NT * CDIM),
                            "r"(NT * CDIM * 4), "r"(mba) : "memory");
            asm volatile("cp.async.bulk.shared::cta.global.mbarrier::complete_tx::bytes [%0], [%1], %2, [%3];"
                         :: "r"(smem_u32(ms + nb * MS_F)), "l"(mb + (size_t)jt * NT * KH),
                            "r"(NT * KH * 4), "r"(mba) : "memory");
        }

        // 2. compute tile it from xs[buf], ws[buf]
        {
            const float* xsb = xs + buf * XS_F;
            const float* wsb = ws + buf * WS_F;
            #pragma unroll 2
            for (int n = 0; n < NT; n++) {
                const float* xr = xsb + n * CDIM + h * 64 + ct * 8;
                const ulonglong2 xa = *(const ulonglong2*)xr;
                const ulonglong2 xc = *(const ulonglong2*)(xr + 4);
                const uint64_t xq[4] = {xa.x, xa.y, xc.x, xc.y};

                const float* wbase = wsb + (n * HH + h) * 32 + mt * 8;
                const float4 w03 = *(const float4*)wbase;
                const float2 w45 = *(const float2*)(wbase + 4);
                const float  w6  = wbase[6];
                const float wv[7] = {w03.x, w03.y, w03.z, w03.w, w45.x, w45.y, w6};

                uint64_t wp7[7];
                #pragma unroll
                for (int i = 0; i < 7; i++) wp7[i] = pk2(wv[i], wv[i]);

                #pragma unroll
                for (int i = 0; i < 7; i++)
                    #pragma unroll
                    for (int j = 0; j < 4; j++)
                        fma2(acc[i][j], wp7[i], xq[j]);
            }
        }

        // 3. wait tile jt, build ws[nb] (ws[nb] not read this iteration)
        if (hn) {
            {
                uint32_t mba = smem_u32(&mbar[nb]);
                MBAR_WAIT(mba, ph[nb]);
                ph[nb] ^= 1;
            }
            const float* msb = ms + nb * MS_F;
            float* wsn = ws + nb * WS_F;
            for (int p = t; p < NT * (MT / 2); p += TPB2) {
                const int nn = p / (MT / 2);
                const int lm = 2 * (p % (MT / 2));
                const int s0 = (lm / 7) * 8 + lm % 7;
                const int s1 = ((lm + 1) / 7) * 8 + (lm + 1) % 7;
                const float2* wp = (const float2*)(WB + (size_t)(jt * NT + nn) * NTOK + m0 + lm);
                const float* msn = msb + nn * KH;
                uint64_t wacc[HH];
                #pragma unroll
                for (int hh = 0; hh < HH; hh++) wacc[hh] = 0ull;
                #pragma unroll 4
                for (int k = 0; k < KB; k++) {
                    const float2 w2 = __ldg(wp + k * NN2);
                    const uint64_t wq = pk2(w2.x, w2.y);
                    const float2 m01 = *(const float2*)(msn + k * HH);
                    const float2 m23 = *(const float2*)(msn + k * HH + 2);
                    const float2 m45 = *(const float2*)(msn + k * HH + 4);
                    fma2(wacc[0], pk2(m01.x, m01.x), wq);
                    fma2(wacc[1], pk2(m01.y, m01.y), wq);
                    fma2(wacc[2], pk2(m23.x, m23.x), wq);
                    fma2(wacc[3], pk2(m23.y, m23.y), wq);
                    fma2(wacc[4], pk2(m45.x, m45.x), wq);
                    fma2(wacc[5], pk2(m45.y, m45.y), wq);
                }
                #pragma unroll
                for (int hh = 0; hh < HH; hh++) {
                    float f0, f1; up2(wacc[hh], f0, f1);
                    float* wd = wsn + (nn * HH + hh) * 32;
                    wd[s0] = f0; wd[s1] = f1;
                }
            }
        }
        __syncthreads();
    }

    // ---- epilogue: out[b][m0 + mt*7 + i][h*64 + ct*8 + j] ----
    #pragma unroll
    for (int i = 0; i < 7; i++) {
        const int m = m0 + mt * 7 + i;
        float* o = out + ((size_t)b * NTOK + m) * CDIM + h * 64 + ct * 8;
        float4 o1, o2;
        up2(acc[i][0], o1.x, o1.y);
        up2(acc[i][1], o1.z, o1.w);
        up2(acc[i][2], o2.x, o2.y);
        up2(acc[i][3], o2.z, o2.w);
        *(float4*)(o)     = o1;
        *(float4*)(o + 4) = o2;
    }
}

// ---------------------------------------------------------------------------
extern "C" void kernel_launch(void* const* d_in, const int* in_sizes, int n_in,
                              void* d_out, int out_size)
{
    const float* x  = (const float*)d_in[0];
    const float* W1 = (const float*)d_in[1];
    const float* b1 = (const float*)d_in[2];
    const float* W2 = (const float*)d_in[3];
    const float* b2 = (const float*)d_in[4];
    const float* WB = (const float*)d_in[5];
    float* out = (float*)d_out;

    cudaFuncSetAttribute(mix_kernel, cudaFuncAttributeMaxDynamicSharedMemorySize, SMEM_B);

    adapter_kernel<<<(BSZ * NTOK) / ROWS, TPB1>>>(x, W1, b1, W2, b2);
    mix_kernel<<<dim3(NTOK / MT, BSZ), TPB2, SMEM_B>>>(x, WB, out);
}

// round 12
// speedup vs baseline: 1.5557x; 1.1748x over previous
#include <cuda_runtime.h>
#include <math.h>
#include <stdint.h>

#define BSZ  128
#define NTOK 196
#define CDIM 384
#define KB   16
#define HH   6
#define DR   96   // DIM/R
#define KH   96   // K*H

__device__ __align__(256) float g_mix[BSZ * NTOK * KH];

// ---------------- helpers ----------------
__device__ __forceinline__ uint64_t pk2(float a, float b) {
    uint64_t r; asm("mov.b64 %0,{%1,%2};" : "=l"(r) : "f"(a), "f"(b)); return r;
}
__device__ __forceinline__ void up2(uint64_t v, float& a, float& b) {
    asm("mov.b64 {%0,%1},%2;" : "=f"(a), "=f"(b) : "l"(v));
}
__device__ __forceinline__ void fma2(uint64_t& d, uint64_t a, uint64_t b) {
    asm("fma.rn.f32x2 %0,%1,%2,%0;" : "+l"(d) : "l"(a), "l"(b));
}
__device__ __forceinline__ uint32_t smem_u32(const void* p) {
    uint32_t a;
    asm("{ .reg .u64 t; cvta.to.shared.u64 t, %1; cvt.u32.u64 %0, t; }" : "=r"(a) : "l"(p));
    return a;
}
#define MBAR_WAIT(addr, par) do {                                             \
    uint32_t _done;                                                           \
    asm volatile("{\n\t.reg .pred p;\n\t"                                     \
        "mbarrier.try_wait.parity.acquire.cta.shared::cta.b64 p, [%1], %2;\n\t" \
        "selp.b32 %0, 1, 0, p;\n\t}" : "=r"(_done) : "r"(addr), "r"(par) : "memory"); \
    if (!_done) {                                                             \
        asm volatile("{\n\t.reg .pred P1;\n\t"                                \
            "W_%=:\n\t"                                                       \
            "mbarrier.try_wait.parity.acquire.cta.shared::cta.b64 P1, [%0], %1, 0x989680;\n\t" \
            "@P1 bra.uni D_%=;\n\t"                                           \
            "bra.uni W_%=;\n\t"                                               \
            "D_%=:\n\t}" :: "r"(addr), "r"(par) : "memory");                  \
    }                                                                         \
} while (0)

// ---------------------------------------------------------------------------
// Kernel 1: adapter MLP (Linear -> exact GELU -> Linear) + softmax over K
// REVERTED to the round-3 original (measured ~88-91us; v2 was ~115us).
// ---------------------------------------------------------------------------
#define ROWS 32
#define TPB1 256

__global__ __launch_bounds__(TPB1, 2)
void adapter_kernel(const float* __restrict__ x,
                    const float* __restrict__ W1,
                    const float* __restrict__ b1,
                    const float* __restrict__ W2,
                    const float* __restrict__ b2)
{
    __shared__ float xs[ROWS][CDIM];
    __shared__ float hid[ROWS][DR];
    __shared__ float wst[DR * DR];

    const int t    = threadIdx.x;
    const int row0 = blockIdx.x * ROWS;

    {
        const float4* xg = (const float4*)(x + (size_t)row0 * CDIM);
        float4* xd = (float4*)&xs[0][0];
        for (int i = t; i < ROWS * CDIM / 4; i += TPB1) xd[i] = xg[i];
    }

    const int cg = t & 31;
    const int rg = t >> 5;

    float acc[4][3];
    #pragma unroll
    for (int i = 0; i < 4; i++)
        #pragma unroll
        for (int j = 0; j < 3; j++) acc[i][j] = b1[cg * 3 + j];

    for (int kt = 0; kt < CDIM; kt += 32) {
        __syncthreads();
        for (int i = t; i < 32 * DR; i += TPB1) wst[i] = W1[kt * DR + i];
        __syncthreads();
        #pragma unroll
        for (int kk = 0; kk < 32; kk++) {
            float xv[4], wv[3];
            #pragma unroll
            for (int i = 0; i < 4; i++) xv[i] = xs[rg * 4 + i][kt + kk];
            #pragma unroll
            for (int j = 0; j < 3; j++) wv[j] = wst[kk * DR + cg * 3 + j];
            #pragma unroll
            for (int i = 0; i < 4; i++)
                #pragma unroll
                for (int j = 0; j < 3; j++) acc[i][j] += xv[i] * wv[j];
        }
    }

    #pragma unroll
    for (int i = 0; i < 4; i++)
        #pragma unroll
        for (int j = 0; j < 3; j++) {
            float v = acc[i][j];
            hid[rg * 4 + i][cg * 3 + j] = 0.5f * v * (1.0f + erff(v * 0.70710678118654752f));
        }
    __syncthreads();

    for (int i = t; i < DR * DR; i += TPB1) wst[i] = W2[i];
    __syncthreads();

    float acc2[4][3];
    #pragma unroll
    for (int i = 0; i < 4; i++)
        #pragma unroll
        for (int j = 0; j < 3; j++) acc2[i][j] = b2[cg * 3 + j];

    #pragma unroll 4
    for (int k = 0; k < DR; k++) {
        float xv[4], wv[3];
        #pragma unroll
        for (int i = 0; i < 4; i++) xv[i] = hid[rg * 4 + i][k];
        #pragma unroll
        for (int j = 0; j < 3; j++) wv[j] = wst[k * DR + cg * 3 + j];
        #pragma unroll
        for (int i = 0; i < 4; i++)
            #pragma unroll
            for (int j = 0; j < 3; j++) acc2[i][j] += xv[i] * wv[j];
    }

    float* mr = &xs[0][0];
    #pragma unroll
    for (int i = 0; i < 4; i++)
        #pragma unroll
        for (int j = 0; j < 3; j++)
            mr[(rg * 4 + i) * KH + cg * 3 + j] = acc2[i][j];
    __syncthreads();

    if (t < ROWS * HH) {
        const int r = t / HH, h = t % HH;
        const float* p = mr + r * KH + h;
        float mx = -1e30f;
        #pragma unroll
        for (int k = 0; k < KB; k++) mx = fmaxf(mx, p[k * HH]);
        float e[KB], s = 0.0f;
        #pragma unroll
        for (int k = 0; k < KB; k++) { e[k] = expf(p[k * HH] - mx); s += e[k]; }
        const float inv = 1.0f / s;
        float* og = g_mix + (size_t)(row0 + r) * KH + h;
        #pragma unroll
        for (int k = 0; k < KB; k++) og[k * HH] = e[k] * inv;
    }
}

// ---------------------------------------------------------------------------
// Kernel 2 (v8): warp-specialized producer/consumer.
// 320 thr: warps 0-5 compute (r3 inner loop), warps 6-9 build (TMA + WB gather
// + ws construction). xs/ms triple-buffered, ws double-buffered.
// Rendezvous via alternating named barriers; compute never waits on memory.
// ---------------------------------------------------------------------------
#define NT      14
#define NTILES  14          // 196/14 exact
#define MT      28
#define TPB2    320
#define NCOMP   192

#define XS_F    (NT * CDIM)       // 5376
#define MS_F    (NT * KH)         // 1344
#define WS_F    (NT * HH * 32)    // 2688
#define SMEM_B  ((3 * XS_F + 3 * MS_F + 2 * WS_F) * 4)   // 102144 B

__global__ __launch_bounds__(TPB2, 2)
void mix_kernel(const float* __restrict__ x,
                const float* __restrict__ WB,
                float* __restrict__ out)
{
    extern __shared__ __align__(128) float sm[];
    float* xs = sm;                        // [3][NT][CDIM]
    float* ms = sm + 3 * XS_F;             // [3][NT][KH]
    float* ws = sm + 3 * (XS_F + MS_F);    // [2][NT][HH][32]
    __shared__ __align__(16) uint64_t mbar[3];

    const int b    = blockIdx.y;
    const int m0   = blockIdx.x * MT;
    const int t    = threadIdx.x;
    const int lane = t & 31;

    const float* xb = x     + (size_t)b * NTOK * CDIM;
    const float* mb = g_mix + (size_t)b * NTOK * KH;
    const size_t NN2 = (size_t)NTOK * NTOK / 2;

    if (t == NCOMP) {
        asm volatile("mbarrier.init.shared.b64 [%0], 1;" :: "r"(smem_u32(&mbar[0])) : "memory");
        asm volatile("mbarrier.init.shared.b64 [%0], 1;" :: "r"(smem_u32(&mbar[1])) : "memory");
        asm volatile("mbarrier.init.shared.b64 [%0], 1;" :: "r"(smem_u32(&mbar[2])) : "memory");
    }
    __syncthreads();

    if (t < NCOMP) {
        // ================= CONSUMER: 6 compute warps =================
        const int h  = t >> 5;        // warp == head 0..5
        const int mt = lane >> 3;     // m-group
        const int ct = lane & 7;      // c-group (8 cols)

        uint64_t acc[7][4];
        #pragma unroll
        for (int i = 0; i < 7; i++)
            #pragma unroll
            for (int j = 0; j < 4; j++) acc[i][j] = 0ull;

        for (int it = 0; it < NTILES; it++) {
            asm volatile("bar.sync %0, %1;" :: "r"(1 + (it & 1)), "r"(TPB2) : "memory");

            const float* xsb = xs + (it % 3) * XS_F;
            const float* wsb = ws + (it & 1) * WS_F;
            #pragma unroll 2
            for (int n = 0; n < NT; n++) {
                const float* xr = xsb + n * CDIM + h * 64 + ct * 8;
                const ulonglong2 xa = *(const ulonglong2*)xr;
                const ulonglong2 xc = *(const ulonglong2*)(xr + 4);
                const uint64_t xq[4] = {xa.x, xa.y, xc.x, xc.y};

                const float* wbase = wsb + (n * HH + h) * 32 + mt * 8;
                const float4 w03 = *(const float4*)wbase;
                const float2 w45 = *(const float2*)(wbase + 4);
                const float  w6  = wbase[6];
                const float wv[7] = {w03.x, w03.y, w03.z, w03.w, w45.x, w45.y, w6};

                uint64_t wp7[7];
                #pragma unroll
                for (int i = 0; i < 7; i++) wp7[i] = pk2(wv[i], wv[i]);

                #pragma unroll
                for (int i = 0; i < 7; i++)
                    #pragma unroll
                    for (int j = 0; j < 4; j++)
                        fma2(acc[i][j], wp7[i], xq[j]);
            }
        }

        // epilogue
        #pragma unroll
        for (int i = 0; i < 7; i++) {
            const int m = m0 + mt * 7 + i;
            float* o = out + ((size_t)b * NTOK + m) * CDIM + h * 64 + ct * 8;
            float4 o1, o2;
            up2(acc[i][0], o1.x, o1.y);
            up2(acc[i][1], o1.z, o1.w);
            up2(acc[i][2], o2.x, o2.y);
            up2(acc[i][3], o2.z, o2.w);
            *(float4*)(o)     = o1;
            *(float4*)(o + 4) = o2;
        }
    } else {
        // ================= PRODUCER: 4 build warps (128 thr) =================
        const int bt = t - NCOMP;     // 0..127

        // prologue: TMA tiles 0 and 1
        if (t == NCOMP) {
            #pragma unroll
            for (int pt = 0; pt < 2; pt++) {
                uint32_t mba = smem_u32(&mbar[pt]);
                asm volatile("mbarrier.arrive.expect_tx.shared.b64 _, [%0], %1;"
                             :: "r"(mba), "r"(NT * (CDIM + KH) * 4) : "memory");
                asm volatile("cp.async.bulk.shared::cta.global.mbarrier::complete_tx::bytes [%0], [%1], %2, [%3];"
                             :: "r"(smem_u32(xs + pt * XS_F)), "l"(xb + (size_t)pt * NT * CDIM),
                                "r"(NT * CDIM * 4), "r"(mba) : "memory");
                asm volatile("cp.async.bulk.shared::cta.global.mbarrier::complete_tx::bytes [%0], [%1], %2, [%3];"
                             :: "r"(smem_u32(ms + pt * MS_F)), "l"(mb + (size_t)pt * NT * KH),
                                "r"(NT * KH * 4), "r"(mba) : "memory");
            }
        }

        int phbits = 0;   // per-mbar phase parity bits

        for (int it = 0; it < NTILES; it++) {
            const int mi = it % 3;
            MBAR_WAIT(smem_u32(&mbar[mi]), (phbits >> mi) & 1);
            phbits ^= (1 << mi);

            // build ws[it&1] from ms[mi] + WB rows of tile it
            const float* msb = ms + mi * MS_F;
            float* wsn = ws + (it & 1) * WS_F;
            #pragma unroll
            for (int r = 0; r < 2; r++) {
                const int p = bt + 128 * r;
                if (p < NT * (MT / 2)) {
                    const int nn = p / (MT / 2);
                    const int lm = 2 * (p % (MT / 2));
                    const int s0 = (lm / 7) * 8 + lm % 7;
                    const int s1 = ((lm + 1) / 7) * 8 + (lm + 1) % 7;
                    const float2* wp = (const float2*)(WB + (size_t)(it * NT + nn) * NTOK + m0 + lm);
                    const float* msn = msb + nn * KH;
                    uint64_t wacc[HH];
                    #pragma unroll
                    for (int hh = 0; hh < HH; hh++) wacc[hh] = 0ull;
                    #pragma unroll 4
                    for (int k = 0; k < KB; k++) {
                        const float2 w2 = __ldg(wp + k * NN2);
                        const uint64_t wq = pk2(w2.x, w2.y);
                        const float2 m01 = *(const float2*)(msn + k * HH);
                        const float2 m23 = *(const float2*)(msn + k * HH + 2);
                        const float2 m45 = *(const float2*)(msn + k * HH + 4);
                        fma2(wacc[0], pk2(m01.x, m01.x), wq);
                        fma2(wacc[1], pk2(m01.y, m01.y), wq);
                        fma2(wacc[2], pk2(m23.x, m23.x), wq);
                        fma2(wacc[3], pk2(m23.y, m23.y), wq);
                        fma2(wacc[4], pk2(m45.x, m45.x), wq);
                        fma2(wacc[5], pk2(m45.y, m45.y), wq);
                    }
                    #pragma unroll
                    for (int hh = 0; hh < HH; hh++) {
                        float f0, f1; up2(wacc[hh], f0, f1);
                        float* wd = wsn + (nn * HH + hh) * 32;
                        wd[s0] = f0; wd[s1] = f1;
                    }
                }
            }

            // rendezvous: compute starts C(it); implies C(it-1) finished,
            // so xs/ms slot (it+2)%3 is free for TMA of tile it+2.
            asm volatile("bar.sync %0, %1;" :: "r"(1 + (it & 1)), "r"(TPB2) : "memory");

            if (t == NCOMP && it + 2 < NTILES) {
                const int jt = it + 2, sl = jt % 3;
                uint32_t mba = smem_u32(&mbar[sl]);
                asm volatile("mbarrier.arrive.expect_tx.shared.b64 _, [%0], %1;"
                             :: "r"(mba), "r"(NT * (CDIM + KH) * 4) : "memory");
                asm volatile("cp.async.bulk.shared::cta.global.mbarrier::complete_tx::bytes [%0], [%1], %2, [%3];"
                             :: "r"(smem_u32(xs + sl * XS_F)), "l"(xb + (size_t)jt * NT * CDIM),
                                "r"(NT * CDIM * 4), "r"(mba) : "memory");
                asm volatile("cp.async.bulk.shared::cta.global.mbarrier::complete_tx::bytes [%0], [%1], %2, [%3];"
                             :: "r"(smem_u32(ms + sl * MS_F)), "l"(mb + (size_t)jt * NT * KH),
                                "r"(NT * KH * 4), "r"(mba) : "memory");
            }
        }
    }
}

// ---------------------------------------------------------------------------
extern "C" void kernel_launch(void* const* d_in, const int* in_sizes, int n_in,
                              void* d_out, int out_size)
{
    const float* x  = (const float*)d_in[0];
    const float* W1 = (const float*)d_in[1];
    const float* b1 = (const float*)d_in[2];
    const float* W2 = (const float*)d_in[3];
    const float* b2 = (const float*)d_in[4];
    const float* WB = (const float*)d_in[5];
    float* out = (float*)d_out;

    cudaFuncSetAttribute(mix_kernel, cudaFuncAttributeMaxDynamicSharedMemorySize, SMEM_B);

    adapter_kernel<<<(BSZ * NTOK) / ROWS, TPB1>>>(x, W1, b1, W2, b2);
    mix_kernel<<<dim3(NTOK / MT, BSZ), TPB2, SMEM_B>>>(x, WB, out);
}